// round 15
// baseline (speedup 1.0000x reference)
#include <cuda_runtime.h>
#include <cuda_fp16.h>
#include <cstdint>

#define BB 4
#define TT 2048
#define EE 1024
#define HH 16
#define HD 64

// softmax scale folded into Q at QKV epilogue: 1/sqrt(64) * log2(e)
#define QSCALE (0.125f * 1.44269504f)

// ---------------------------------------------------------------------------
// Scratch (device globals). All activations/weights stored fp16.
// ---------------------------------------------------------------------------
__device__ __align__(16) __half g_qh[BB * HH * TT * HD];   // [B,H,T,HD], pre-scaled
__device__ __align__(16) __half g_kh[BB * HH * TT * HD];
__device__ __align__(16) __half g_vh[BB * HH * TT * HD];
__device__ __align__(16) __half g_atth[BB * TT * EE];      // [B,T,E]
__device__ __align__(16) __half g_wth[3 * EE * EE];        // K-major qkv weights
__device__ __align__(16) __half g_xh[BB * TT * EE];        // x in fp16
__device__ __align__(16) __half g_woh[EE * EE];            // Wo in fp16

// ---------------------------------------------------------------------------
// Helpers
// ---------------------------------------------------------------------------
__device__ __forceinline__ uint32_t smem_u32(const void* p) {
    uint32_t a;
    asm("{ .reg .u64 t; cvta.to.shared.u64 t, %1; cvt.u32.u64 %0, t; }"
        : "=r"(a) : "l"(p));
    return a;
}

__device__ __forceinline__ uint32_t f2h2(float lo, float hi) {
    __half2 h = __floats2half2_rn(lo, hi);
    return *(uint32_t*)&h;
}

// single-instruction exp2 (MUFU.EX2)
__device__ __forceinline__ float ex2(float x) {
    float y;
    asm("ex2.approx.ftz.f32 %0, %1;" : "=f"(y) : "f"(x));
    return y;
}

// m16n8k16 f16 MMA, f32 accumulate (rt~16/SMSP)
__device__ __forceinline__ void mma16(float c[4],
                                      uint32_t a0, uint32_t a1, uint32_t a2, uint32_t a3,
                                      uint32_t b0, uint32_t b1) {
    asm volatile(
        "mma.sync.aligned.m16n8k16.row.col.f32.f16.f16.f32 "
        "{%0,%1,%2,%3},{%4,%5,%6,%7},{%8,%9},{%0,%1,%2,%3};"
        : "+f"(c[0]), "+f"(c[1]), "+f"(c[2]), "+f"(c[3])
        : "r"(a0), "r"(a1), "r"(a2), "r"(a3), "r"(b0), "r"(b1));
}

// m16n8k16 f16 MMA, f16 accumulate (measured ~2x rate: rt~8/SMSP)
__device__ __forceinline__ void mma16h(uint32_t c[2],
                                       uint32_t a0, uint32_t a1, uint32_t a2, uint32_t a3,
                                       uint32_t b0, uint32_t b1) {
    asm volatile(
        "mma.sync.aligned.m16n8k16.row.col.f16.f16.f16.f16 "
        "{%0,%1},{%2,%3,%4,%5},{%6,%7},{%0,%1};"
        : "+r"(c[0]), "+r"(c[1])
        : "r"(a0), "r"(a1), "r"(a2), "r"(a3), "r"(b0), "r"(b1));
}

#define LDSM_X4(r0, r1, r2, r3, addr) \
    asm volatile("ldmatrix.sync.aligned.m8n8.x4.shared.b16 {%0,%1,%2,%3}, [%4];" \
                 : "=r"(r0), "=r"(r1), "=r"(r2), "=r"(r3) : "r"(addr))
#define LDSM_X4T(r0, r1, r2, r3, addr) \
    asm volatile("ldmatrix.sync.aligned.m8n8.x4.trans.shared.b16 {%0,%1,%2,%3}, [%4];" \
                 : "=r"(r0), "=r"(r1), "=r"(r2), "=r"(r3) : "r"(addr))

#define CP16(dst, src) \
    asm volatile("cp.async.cg.shared.global [%0], [%1], 16;" :: "r"(dst), "l"(src))
#define CP_COMMIT()  asm volatile("cp.async.commit_group;" ::: "memory")
#define CP_WAIT1()   asm volatile("cp.async.wait_group 1;" ::: "memory")
#define CP_WAIT0()   asm volatile("cp.async.wait_group 0;" ::: "memory")

// ---------------------------------------------------------------------------
// Single merged pre-pass: x -> g_xh, Wo -> g_woh, Wq/Wk/Wv -> g_wth (K-major).
// Block ranges: [0,NBX) x-convert, [NBX,NBX+NBW) Wo-convert, rest transpose.
// ROUND-15 FIX: NBX = 8192 (was 2048 — only 1/4 of x converted => rel_err 0.67).
// ---------------------------------------------------------------------------
#define NBX 8192   // (4*2048*1024/4) / 256
#define NBW 1024   // (1024*1024/4) / 256
#define NBT 3072   // 32 k-tiles * 32 (h*2+dhalf) * 3 matrices

__global__ __launch_bounds__(256) void prep_kernel(
    const float4* __restrict__ x4,  uint2* __restrict__ xh4,
    const float4* __restrict__ wo4, uint2* __restrict__ woh4,
    const float* __restrict__ Wq,
    const float* __restrict__ Wk,
    const float* __restrict__ Wv)
{
    const int bid = blockIdx.x;
    const int tid = threadIdx.x;

    if (bid < NBX) {
        int i = bid * 256 + tid;
        float4 v = x4[i];
        xh4[i] = make_uint2(f2h2(v.x, v.y), f2h2(v.z, v.w));
    } else if (bid < NBX + NBW) {
        int i = (bid - NBX) * 256 + tid;
        float4 v = wo4[i];
        woh4[i] = make_uint2(f2h2(v.x, v.y), f2h2(v.z, v.w));
    } else {
        const int bt  = bid - (NBX + NBW);
        const int m   = bt >> 10;            // matrix 0..2
        const int rem = bt & 1023;
        const int yy  = rem >> 5;            // 0..31 = h*2 + dhalf
        const int k0  = (rem & 31) * 32;
        const int h   = yy >> 1;
        const int d0  = (yy & 1) * 32;

        const float* Ws[3] = {Wq, Wk, Wv};
        __shared__ float tile[32][33];
        const int tx = tid & 31;
        const int ty = tid >> 5;             // 0..7

        const float* src = Ws[m] + (size_t)h * EE * HD;
        #pragma unroll
        for (int i = 0; i < 4; i++)
            tile[ty + 8 * i][tx] = src[(size_t)(k0 + ty + 8 * i) * HD + d0 + tx];
        __syncthreads();

        #pragma unroll
        for (int i = 0; i < 4; i++) {
            int n = m * 1024 + h * 64 + d0 + ty + 8 * i;
            g_wth[(size_t)n * EE + k0 + tx] = __float2half_rn(tile[tx][ty + 8 * i]);
        }
    }
}

// ---------------------------------------------------------------------------
// fp16 mma.sync GEMM — chunked f16 accumulation (rt8 HMMA) with per-chunk
// promotion into f32 master accumulators. Chunk = K64 (4 f16 roundings at
// running rms <=0.15 -> ~3.8e-4 added rel err; gate is 1e-3).
// Processed in two i-halves so f16 accum regs stay at 16 (fits 128-reg cap,
// 2 blocks/SM). Fragments via ldmatrix.x4 (round-8/9-proven addressing).
// Block 128x128, 8 warps (64x32 warp tiles), 2-stage cp.async, stride 72.
// mode 0: QKV  (A=g_xh, B=g_wth; scatter half -> g_qh(*QSCALE)/g_kh/g_vh)
// mode 1: OPROJ(A=g_atth, B=g_woh; out = C + bo, f32)
// ---------------------------------------------------------------------------
#define SA 72
#define ABUF (128 * SA)

__global__ __launch_bounds__(256, 2) void gemm_h_kernel(
    int mode,
    const __half* __restrict__ A,
    const __half* __restrict__ Bsrc,
    const float* __restrict__ bias,
    float* __restrict__ out)
{
    extern __shared__ __half smh[];
    __half* Ah = smh;                 // [2][128*72]
    __half* Bh = smh + 2 * ABUF;      // [2][128*72]

    const int tid  = threadIdx.x;
    const int lane = tid & 31;
    const int wid  = tid >> 5;
    const int wm   = (wid >> 2) * 64;
    const int wn   = (wid & 3) * 32;
    const int r    = lane >> 2;
    const int qd   = lane & 3;

    const int m0 = blockIdx.y * 128;
    const int n0 = blockIdx.x * 128;

    const uint32_t ah0 = smem_u32(Ah);
    const uint32_t bh0 = smem_u32(Bh);

    // ldmatrix x4 lane addressing: lanes 0-15 rows, 16-31 same rows k+8
    const int l_row  = lane & 15;
    const int l_koff = (lane & 16) ? 8 : 0;

    float c[4][4][4] = {};

    auto issue = [&](int cidx) {
        const int p  = cidx & 1;
        const int k0 = cidx * 64;
        #pragma unroll
        for (int rr = 0; rr < 4; rr++) {
            int it  = tid + 256 * rr;
            int row = it >> 3;
            int c8  = it & 7;
            uint32_t off = (uint32_t)(p * ABUF + row * SA + c8 * 8) * 2u;
            CP16(ah0 + off, A + (size_t)(m0 + row) * EE + k0 + c8 * 8);
            CP16(bh0 + off, Bsrc + (size_t)(n0 + row) * EE + k0 + c8 * 8);
        }
        CP_COMMIT();
    };

    issue(0);
    for (int cc = 0; cc < 16; cc++) {
        const int p = cc & 1;
        if (cc + 1 < 16) { issue(cc + 1); CP_WAIT1(); }
        else             { CP_WAIT0(); }
        __syncthreads();

        const uint32_t ap = ah0 + (uint32_t)(p * ABUF) * 2u;
        const uint32_t bp = bh0 + (uint32_t)(p * ABUF) * 2u;

        // two i-halves: 16 live f16-accum regs each; B frags loaded per half
        #pragma unroll
        for (int ih = 0; ih < 2; ih++) {
            uint32_t ch[2][4][2];
            #pragma unroll
            for (int i2 = 0; i2 < 2; i2++)
                #pragma unroll
                for (int j = 0; j < 4; j++) { ch[i2][j][0] = 0u; ch[i2][j][1] = 0u; }

            #pragma unroll
            for (int s = 0; s < 4; s++) {
                const uint32_t soff = (uint32_t)(s * 16 + l_koff) * 2u;
                uint32_t a[2][4];
                #pragma unroll
                for (int i2 = 0; i2 < 2; i2++) {
                    const int i = ih * 2 + i2;
                    LDSM_X4(a[i2][0], a[i2][1], a[i2][2], a[i2][3],
                            ap + (uint32_t)((wm + i * 16 + l_row) * SA) * 2u + soff);
                }
                uint32_t b[4][2];
                #pragma unroll
                for (int jj = 0; jj < 2; jj++) {
                    uint32_t r0, r1, r2, r3;
                    LDSM_X4(r0, r1, r2, r3,
                            bp + (uint32_t)((wn + jj * 16 + l_row) * SA) * 2u + soff);
                    b[2 * jj][0] = r0;      b[2 * jj][1] = r2;
                    b[2 * jj + 1][0] = r1;  b[2 * jj + 1][1] = r3;
                }
                #pragma unroll
                for (int j = 0; j < 4; j++)
                    #pragma unroll
                    for (int i2 = 0; i2 < 2; i2++)
                        mma16h(ch[i2][j], a[i2][0], a[i2][1], a[i2][2], a[i2][3],
                               b[j][0], b[j][1]);
            }

            // promote chunk result into f32 masters
            #pragma unroll
            for (int i2 = 0; i2 < 2; i2++) {
                const int i = ih * 2 + i2;
                #pragma unroll
                for (int j = 0; j < 4; j++) {
                    float2 lo = __half22float2(*(__half2*)&ch[i2][j][0]);
                    float2 hi = __half22float2(*(__half2*)&ch[i2][j][1]);
                    c[i][j][0] += lo.x;  c[i][j][1] += lo.y;
                    c[i][j][2] += hi.x;  c[i][j][3] += hi.y;
                }
            }
        }
        __syncthreads();
    }

    // ---- epilogue ----
    #pragma unroll
    for (int i = 0; i < 4; i++) {
        const int gm0 = m0 + wm + i * 16 + r;     // rows for c0/c1; +8 for c2/c3
        if (mode == 0) {
            const int b_ = gm0 >> 11;
            const int t  = gm0 & 2047;
            #pragma unroll
            for (int j = 0; j < 4; j++) {
                const int col = n0 + wn + j * 8 + qd * 2;
                const int mat = col >> 10;
                const int rem = col & 1023;
                const int h   = rem >> 6;
                const int d   = rem & 63;
                __half* base = (mat == 0) ? g_qh : (mat == 1 ? g_kh : g_vh);
                const float sc = (mat == 0) ? QSCALE : 1.0f;
                size_t o0 = ((size_t)((b_ * 16 + h) * 2048 + t)) * 64 + d;
                *(uint32_t*)(base + o0) =
                    f2h2(c[i][j][0] * sc, c[i][j][1] * sc);
                *(uint32_t*)(base + o0 + 8 * 64) =
                    f2h2(c[i][j][2] * sc, c[i][j][3] * sc);
            }
        } else {
            #pragma unroll
            for (int j = 0; j < 4; j++) {
                const int col = n0 + wn + j * 8 + qd * 2;
                float2 bv = *(const float2*)(bias + col);
                float* d0 = out + (size_t)gm0 * EE + col;
                *(float2*)d0            = make_float2(c[i][j][0] + bv.x, c[i][j][1] + bv.y);
                *(float2*)(d0 + 8 * EE) = make_float2(c[i][j][2] + bv.x, c[i][j][3] + bv.y);
            }
        }
    }
}

// ---------------------------------------------------------------------------
// Causal flash attention — UNCHANGED from round 13 (static softmax, f16-accum
// S, ldmatrix.x4 frags, register-resident P, j-pair causal skip, MUFU ex2).
// ---------------------------------------------------------------------------
#define AM 128
#define SK 72
#define KVBUF (64 * SK)

__global__ __launch_bounds__(256, 2) void attn_kernel()
{
    extern __shared__ __half smk[];
    __half* K0 = smk;                  // [2][64][72]
    __half* V0 = smk + 2 * KVBUF;      // [2][64][72]

    const uint32_t k0a = smem_u32(K0);
    const uint32_t v0a = smem_u32(V0);

    const int bh = blockIdx.x;
    const int b  = bh >> 4;
    const int h  = bh & 15;
    const int q0 = TT - AM - blockIdx.y * AM;   // y=0 -> longest; global LPT

    const int tid  = threadIdx.x;
    const int lane = tid & 31;
    const int wid  = tid >> 5;
    const int wm   = wid * 16;
    const int r    = lane >> 2;
    const int qd   = lane & 3;

    const __half* qg = g_qh + ((size_t)bh * TT + q0) * HD;
    const __half* kg = g_kh + (size_t)bh * TT * HD;
    const __half* vg = g_vh + (size_t)bh * TT * HD;

    auto issueKV = [&](int t) {
        const int p  = t & 1;
        const int s0 = t * 64;
        #pragma unroll
        for (int rr = 0; rr < 2; rr++) {
            int it  = tid + 256 * rr;
            int row = it >> 3;
            int c8  = it & 7;
            uint32_t off = (uint32_t)(p * KVBUF + row * SK + c8 * 8) * 2u;
            CP16(k0a + off, kg + (size_t)(s0 + row) * 64 + c8 * 8);
            CP16(v0a + off, vg + (size_t)(s0 + row) * 64 + c8 * 8);
        }
        CP_COMMIT();
    };

    const int nt = q0 / 64 + 2;
    issueKV(0);

    uint32_t qa[4][4];
    {
        const __half* q0p = qg + (size_t)(wm + r) * 64 + 2 * qd;
        #pragma unroll
        for (int s = 0; s < 4; s++) {
            qa[s][0] = *(const uint32_t*)(q0p + s * 16);
            qa[s][1] = *(const uint32_t*)(q0p + 8 * 64 + s * 16);
            qa[s][2] = *(const uint32_t*)(q0p + s * 16 + 8);
            qa[s][3] = *(const uint32_t*)(q0p + 8 * 64 + s * 16 + 8);
        }
    }

    const int k_rowgrp = (lane >> 4) & 1;
    const int k_row    = lane & 7;
    const int k_koff   = (lane >> 3) & 1;
    const int v_row    = lane & 15;
    const int v_cg     = lane >> 4;

    float o[8][4] = {};
    float l0 = 0.f, l1 = 0.f;

    for (int t = 0; t < nt; t++) {
        const int p  = t & 1;
        const int s0 = t * 64;
        if (t + 1 < nt) { issueKV(t + 1); CP_WAIT1(); }
        else            { CP_WAIT0(); }
        __syncthreads();

        const int lim = q0 + wm + 15 - s0;
        if (lim >= 0) {
            const uint32_t ksa = k0a + (uint32_t)(p * KVBUF) * 2u;
            const uint32_t vsa = v0a + (uint32_t)(p * KVBUF) * 2u;
            const bool full = (s0 + 63 <= q0 + wm);

            if (full) {
                uint32_t ch[8][2];
                #pragma unroll
                for (int j = 0; j < 8; j++) { ch[j][0] = 0u; ch[j][1] = 0u; }

                #pragma unroll
                for (int s = 0; s < 4; s++) {
                    #pragma unroll
                    for (int jb = 0; jb < 8; jb += 2) {
                        uint32_t kaddr = ksa + (uint32_t)(
                            ((jb + k_rowgrp) * 8 + k_row) * SK + s * 16 + k_koff * 8) * 2u;
                        uint32_t b0, b1, b2, b3;
                        LDSM_X4(b0, b1, b2, b3, kaddr);
                        mma16h(ch[jb],     qa[s][0], qa[s][1], qa[s][2], qa[s][3], b0, b1);
                        mma16h(ch[jb + 1], qa[s][0], qa[s][1], qa[s][2], qa[s][3], b2, b3);
                    }
                }

                uint32_t ph[4][4];
                #pragma unroll
                for (int j = 0; j < 8; j++) {
                    float2 v01 = __half22float2(*(__half2*)&ch[j][0]);
                    float2 v23 = __half22float2(*(__half2*)&ch[j][1]);
                    v01.x = ex2(v01.x);  v01.y = ex2(v01.y);
                    v23.x = ex2(v23.x);  v23.y = ex2(v23.y);
                    l0 += v01.x + v01.y;
                    l1 += v23.x + v23.y;
                    const int s_ = j >> 1;
                    if ((j & 1) == 0) {
                        ph[s_][0] = f2h2(v01.x, v01.y);
                        ph[s_][1] = f2h2(v23.x, v23.y);
                    } else {
                        ph[s_][2] = f2h2(v01.x, v01.y);
                        ph[s_][3] = f2h2(v23.x, v23.y);
                    }
                }

                #pragma unroll
                for (int s = 0; s < 4; s++) {
                    #pragma unroll
                    for (int jb = 0; jb < 8; jb += 2) {
                        uint32_t vaddr = vsa + (uint32_t)(
                            (s * 16 + v_row) * SK + (jb + v_cg) * 8) * 2u;
                        uint32_t vb0, vb1, vb2, vb3;
                        LDSM_X4T(vb0, vb1, vb2, vb3, vaddr);
                        mma16(o[jb],     ph[s][0], ph[s][1], ph[s][2], ph[s][3], vb0, vb1);
                        mma16(o[jb + 1], ph[s][0], ph[s][1], ph[s][2], ph[s][3], vb2, vb3);
                    }
                }
            } else {
                const int spairs = min(4, (lim >> 4) + 1);

                uint32_t ch[8][2];
                #pragma unroll
                for (int j = 0; j < 8; j++) { ch[j][0] = 0u; ch[j][1] = 0u; }

                for (int sp = 0; sp < spairs; sp++) {
                    const int jb = sp * 2;
                    #pragma unroll
                    for (int s = 0; s < 4; s++) {
                        uint32_t kaddr = ksa + (uint32_t)(
                            ((jb + k_rowgrp) * 8 + k_row) * SK + s * 16 + k_koff * 8) * 2u;
                        uint32_t b0, b1, b2, b3;
                        LDSM_X4(b0, b1, b2, b3, kaddr);
                        mma16h(ch[jb],     qa[s][0], qa[s][1], qa[s][2], qa[s][3], b0, b1);
                        mma16h(ch[jb + 1], qa[s][0], qa[s][1], qa[s][2], qa[s][3], b2, b3);
                    }
                }

                const int row0 = q0 + wm + r, row1 = row0 + 8;
                uint32_t ph[4][4];
                for (int sp = 0; sp < spairs; sp++) {
                    #pragma unroll
                    for (int jj = 0; jj < 2; jj++) {
                        const int j = sp * 2 + jj;
                        float2 v01 = __half22float2(*(__half2*)&ch[j][0]);
                        float2 v23 = __half22float2(*(__half2*)&ch[j][1]);
                        const int cl = s0 + j * 8 + qd * 2;
                        if (cl     > row0) v01.x = -1e30f;
                        if (cl + 1 > row0) v01.y = -1e30f;
                        if (cl     > row1) v23.x = -1e30f;
                        if (cl + 1 > row1) v23.y = -1e30f;
                        v01.x = ex2(v01.x);  v01.y = ex2(v01.y);
                        v23.x = ex2(v23.x);  v23.y = ex2(v23.y);
                        l0 += v01.x + v01.y;
                        l1 += v23.x + v23.y;
                        if (jj == 0) {
                            ph[sp][0] = f2h2(v01.x, v01.y);
                            ph[sp][1] = f2h2(v23.x, v23.y);
                        } else {
                            ph[sp][2] = f2h2(v01.x, v01.y);
                            ph[sp][3] = f2h2(v23.x, v23.y);
                        }
                    }
                }

                for (int sp = 0; sp < spairs; sp++) {
                    #pragma unroll
                    for (int jb = 0; jb < 8; jb += 2) {
                        uint32_t vaddr = vsa + (uint32_t)(
                            (sp * 16 + v_row) * SK + (jb + v_cg) * 8) * 2u;
                        uint32_t vb0, vb1, vb2, vb3;
                        LDSM_X4T(vb0, vb1, vb2, vb3, vaddr);
                        mma16(o[jb],     ph[sp][0], ph[sp][1], ph[sp][2], ph[sp][3], vb0, vb1);
                        mma16(o[jb + 1], ph[sp][0], ph[sp][1], ph[sp][2], ph[sp][3], vb2, vb3);
                    }
                }
            }
        }
        __syncthreads();
    }

    // ---- epilogue: quad-reduce l, normalize, store half to g_atth ----
    l0 += __shfl_xor_sync(0xffffffffu, l0, 1);
    l0 += __shfl_xor_sync(0xffffffffu, l0, 2);
    l1 += __shfl_xor_sync(0xffffffffu, l1, 1);
    l1 += __shfl_xor_sync(0xffffffffu, l1, 2);
    const float inv0 = 1.0f / l0, inv1 = 1.0f / l1;
    const int t0 = q0 + wm + r;
    __half* og0 = g_atth + ((size_t)b * TT + t0) * EE + h * 64;
    __half* og1 = og0 + 8 * EE;
    #pragma unroll
    for (int j = 0; j < 8; j++) {
        *(uint32_t*)(og0 + j * 8 + qd * 2) = f2h2(o[j][0] * inv0, o[j][1] * inv0);
        *(uint32_t*)(og1 + j * 8 + qd * 2) = f2h2(o[j][2] * inv1, o[j][3] * inv1);
    }
}

// ---------------------------------------------------------------------------
extern "C" void kernel_launch(void* const* d_in, const int* in_sizes, int n_in,
                              void* d_out, int out_size)
{
    const float* x  = (const float*)d_in[0];
    const float* Wq = (const float*)d_in[1];
    const float* Wk = (const float*)d_in[2];
    const float* Wv = (const float*)d_in[3];
    const float* Wo = (const float*)d_in[4];
    const float* bo = (const float*)d_in[5];
    float* out = (float*)d_out;

    __half *wt_ptr, *att_ptr, *xh_ptr, *wo_ptr;
    cudaGetSymbolAddress((void**)&wt_ptr,  g_wth);
    cudaGetSymbolAddress((void**)&att_ptr, g_atth);
    cudaGetSymbolAddress((void**)&xh_ptr,  g_xh);
    cudaGetSymbolAddress((void**)&wo_ptr,  g_woh);

    // 1) single merged pre-pass (x convert, Wo convert, Wqkv transpose)
    prep_kernel<<<NBX + NBW + NBT, 256>>>(
        (const float4*)x,  (uint2*)xh_ptr,
        (const float4*)Wo, (uint2*)wo_ptr,
        Wq, Wk, Wv);

    const int gemm_smem = 4 * ABUF * sizeof(__half);          // 73728 B
    cudaFuncSetAttribute(gemm_h_kernel,
                         cudaFuncAttributeMaxDynamicSharedMemorySize, gemm_smem);
    const int attn_smem = 4 * KVBUF * sizeof(__half);         // 36864 B
    cudaFuncSetAttribute(attn_kernel,
                         cudaFuncAttributeMaxDynamicSharedMemorySize, attn_smem);

    // 2) QKV: [8192,3072] = g_xh @ g_wth^T  (half scatter -> g_qh/g_kh/g_vh)
    {
        dim3 grid(3 * EE / 128, (BB * TT) / 128);   // (24, 64)
        gemm_h_kernel<<<grid, 256, gemm_smem>>>(0, xh_ptr, wt_ptr, nullptr, nullptr);
    }

    // 3) attention — grid (bh, qtile): global longest-first
    {
        dim3 gridB(BB * HH, TT / AM);               // (64, 16)
        attn_kernel<<<gridB, 256, attn_smem>>>();
    }

    // 4) O projection: out = g_atth @ g_woh^T + bo
    {
        dim3 grid(EE / 128, (BB * TT) / 128);       // (8, 64)
        gemm_h_kernel<<<grid, 256, gemm_smem>>>(1, att_ptr, wo_ptr, bo, out);
    }
}

// round 16
// speedup vs baseline: 1.1176x; 1.1176x over previous
#include <cuda_runtime.h>
#include <cuda_fp16.h>
#include <cstdint>

#define BB 4
#define TT 2048
#define EE 1024
#define HH 16
#define HD 64

// softmax scale folded into Q at QKV epilogue: 1/sqrt(64) * log2(e)
#define QSCALE (0.125f * 1.44269504f)

// ---------------------------------------------------------------------------
// Scratch (device globals). All activations/weights stored fp16.
// ---------------------------------------------------------------------------
__device__ __align__(16) __half g_qh[BB * HH * TT * HD];   // [B,H,T,HD], pre-scaled
__device__ __align__(16) __half g_kh[BB * HH * TT * HD];
__device__ __align__(16) __half g_vh[BB * HH * TT * HD];
__device__ __align__(16) __half g_atth[BB * TT * EE];      // [B,T,E]
__device__ __align__(16) __half g_wth[3 * EE * EE];        // K-major qkv weights
__device__ __align__(16) __half g_xh[BB * TT * EE];        // x in fp16
__device__ __align__(16) __half g_woh[EE * EE];            // Wo in fp16

// ---------------------------------------------------------------------------
// Helpers
// ---------------------------------------------------------------------------
__device__ __forceinline__ uint32_t smem_u32(const void* p) {
    uint32_t a;
    asm("{ .reg .u64 t; cvta.to.shared.u64 t, %1; cvt.u32.u64 %0, t; }"
        : "=r"(a) : "l"(p));
    return a;
}

__device__ __forceinline__ uint32_t f2h2(float lo, float hi) {
    __half2 h = __floats2half2_rn(lo, hi);
    return *(uint32_t*)&h;
}

// single-instruction exp2 (MUFU.EX2)
__device__ __forceinline__ float ex2(float x) {
    float y;
    asm("ex2.approx.ftz.f32 %0, %1;" : "=f"(y) : "f"(x));
    return y;
}

// m16n8k16 f16 MMA, f32 accumulate
__device__ __forceinline__ void mma16(float c[4],
                                      uint32_t a0, uint32_t a1, uint32_t a2, uint32_t a3,
                                      uint32_t b0, uint32_t b1) {
    asm volatile(
        "mma.sync.aligned.m16n8k16.row.col.f32.f16.f16.f32 "
        "{%0,%1,%2,%3},{%4,%5,%6,%7},{%8,%9},{%0,%1,%2,%3};"
        : "+f"(c[0]), "+f"(c[1]), "+f"(c[2]), "+f"(c[3])
        : "r"(a0), "r"(a1), "r"(a2), "r"(a3), "r"(b0), "r"(b1));
}

// m16n8k16 f16 MMA, f16 accumulate (same pipe rate as f32-accum — round-15
// measurement; kept ONLY in attention's S where it also saves unpack work)
__device__ __forceinline__ void mma16h(uint32_t c[2],
                                       uint32_t a0, uint32_t a1, uint32_t a2, uint32_t a3,
                                       uint32_t b0, uint32_t b1) {
    asm volatile(
        "mma.sync.aligned.m16n8k16.row.col.f16.f16.f16.f16 "
        "{%0,%1},{%2,%3,%4,%5},{%6,%7},{%0,%1};"
        : "+r"(c[0]), "+r"(c[1])
        : "r"(a0), "r"(a1), "r"(a2), "r"(a3), "r"(b0), "r"(b1));
}

#define LDSM_X4(r0, r1, r2, r3, addr) \
    asm volatile("ldmatrix.sync.aligned.m8n8.x4.shared.b16 {%0,%1,%2,%3}, [%4];" \
                 : "=r"(r0), "=r"(r1), "=r"(r2), "=r"(r3) : "r"(addr))
#define LDSM_X4T(r0, r1, r2, r3, addr) \
    asm volatile("ldmatrix.sync.aligned.m8n8.x4.trans.shared.b16 {%0,%1,%2,%3}, [%4];" \
                 : "=r"(r0), "=r"(r1), "=r"(r2), "=r"(r3) : "r"(addr))

#define CP16(dst, src) \
    asm volatile("cp.async.cg.shared.global [%0], [%1], 16;" :: "r"(dst), "l"(src))
#define CP_COMMIT()  asm volatile("cp.async.commit_group;" ::: "memory")
#define CP_WAIT1()   asm volatile("cp.async.wait_group 1;" ::: "memory")
#define CP_WAIT0()   asm volatile("cp.async.wait_group 0;" ::: "memory")

// ---------------------------------------------------------------------------
// Single merged pre-pass: x -> g_xh, Wo -> g_woh, Wq/Wk/Wv -> g_wth (K-major).
// NBX covers ALL of x: (4*2048*1024/4)/256 = 8192 blocks.
// ---------------------------------------------------------------------------
#define NBX 8192
#define NBW 1024   // (1024*1024/4) / 256
#define NBT 3072   // 32 k-tiles * 32 (h*2+dhalf) * 3 matrices

__global__ __launch_bounds__(256) void prep_kernel(
    const float4* __restrict__ x4,  uint2* __restrict__ xh4,
    const float4* __restrict__ wo4, uint2* __restrict__ woh4,
    const float* __restrict__ Wq,
    const float* __restrict__ Wk,
    const float* __restrict__ Wv)
{
    const int bid = blockIdx.x;
    const int tid = threadIdx.x;

    if (bid < NBX) {
        int i = bid * 256 + tid;
        float4 v = x4[i];
        xh4[i] = make_uint2(f2h2(v.x, v.y), f2h2(v.z, v.w));
    } else if (bid < NBX + NBW) {
        int i = (bid - NBX) * 256 + tid;
        float4 v = wo4[i];
        woh4[i] = make_uint2(f2h2(v.x, v.y), f2h2(v.z, v.w));
    } else {
        const int bt  = bid - (NBX + NBW);
        const int m   = bt >> 10;            // matrix 0..2
        const int rem = bt & 1023;
        const int yy  = rem >> 5;            // 0..31 = h*2 + dhalf
        const int k0  = (rem & 31) * 32;
        const int h   = yy >> 1;
        const int d0  = (yy & 1) * 32;

        const float* Ws[3] = {Wq, Wk, Wv};
        __shared__ float tile[32][33];
        const int tx = tid & 31;
        const int ty = tid >> 5;             // 0..7

        const float* src = Ws[m] + (size_t)h * EE * HD;
        #pragma unroll
        for (int i = 0; i < 4; i++)
            tile[ty + 8 * i][tx] = src[(size_t)(k0 + ty + 8 * i) * HD + d0 + tx];
        __syncthreads();

        #pragma unroll
        for (int i = 0; i < 4; i++) {
            int n = m * 1024 + h * 64 + d0 + ty + 8 * i;
            g_wth[(size_t)n * EE + k0 + tx] = __float2half_rn(tile[tx][ty + 8 * i]);
        }
    }
}

// ---------------------------------------------------------------------------
// fp16 mma.sync GEMM — round-13 compute core (scalar-LDS fragments, f32
// accumulate; measured best) + 3-stage cp.async pipeline with a SINGLE
// __syncthreads per chunk (round-8-proven barrier schedule).
// C[M,N] = A[M,K] @ B[N,K]^T. Block 128x128, 8 warps (64x32 warp tiles),
// K-chunk 64 halves, stride 72.
// mode 0: QKV  (A=g_xh, B=g_wth; scatter half -> g_qh(*QSCALE)/g_kh/g_vh)
// mode 1: OPROJ(A=g_atth, B=g_woh; out = C + bo, f32)
// SMEM: 6 * 128*72 halves = 110592 B  -> 2 blocks/SM.
// ---------------------------------------------------------------------------
#define SA 72
#define ABUF (128 * SA)
#define NC 16

__global__ __launch_bounds__(256, 2) void gemm_h_kernel(
    int mode,
    const __half* __restrict__ A,
    const __half* __restrict__ Bsrc,
    const float* __restrict__ bias,
    float* __restrict__ out)
{
    extern __shared__ __half smh[];
    __half* Ah = smh;                 // [3][128*72]
    __half* Bh = smh + 3 * ABUF;      // [3][128*72]

    const int tid  = threadIdx.x;
    const int lane = tid & 31;
    const int wid  = tid >> 5;
    const int wm   = (wid >> 2) * 64;
    const int wn   = (wid & 3) * 32;
    const int r    = lane >> 2;
    const int qd   = lane & 3;

    const int m0 = blockIdx.y * 128;
    const int n0 = blockIdx.x * 128;

    const uint32_t ah0 = smem_u32(Ah);
    const uint32_t bh0 = smem_u32(Bh);

    float c[4][4][4] = {};

    auto issue = [&](int cidx) {
        const int p  = cidx % 3;
        const int k0 = cidx * 64;
        #pragma unroll
        for (int rr = 0; rr < 4; rr++) {
            int it  = tid + 256 * rr;
            int row = it >> 3;
            int c8  = it & 7;
            uint32_t off = (uint32_t)(p * ABUF + row * SA + c8 * 8) * 2u;
            CP16(ah0 + off, A + (size_t)(m0 + row) * EE + k0 + c8 * 8);
            CP16(bh0 + off, Bsrc + (size_t)(n0 + row) * EE + k0 + c8 * 8);
        }
        CP_COMMIT();
    };

    issue(0);
    issue(1);

    for (int cc = 0; cc < NC; cc++) {
        if (cc == NC - 1) { CP_WAIT0(); }
        else              { CP_WAIT1(); }
        __syncthreads();
        if (cc + 2 < NC) issue(cc + 2);

        const int p = cc % 3;
        const __half* ap = Ah + p * ABUF;
        const __half* bp = Bh + p * ABUF;
        #pragma unroll
        for (int s = 0; s < 4; s++) {
            uint32_t a[4][4];
            #pragma unroll
            for (int i = 0; i < 4; i++) {
                const __half* arow = ap + (wm + i * 16 + r) * SA + s * 16 + 2 * qd;
                a[i][0] = *(const uint32_t*)(arow);
                a[i][1] = *(const uint32_t*)(arow + 8 * SA);
                a[i][2] = *(const uint32_t*)(arow + 8);
                a[i][3] = *(const uint32_t*)(arow + 8 * SA + 8);
            }
            #pragma unroll
            for (int j = 0; j < 4; j++) {
                const __half* brow = bp + (wn + j * 8 + r) * SA + s * 16 + 2 * qd;
                uint32_t b0 = *(const uint32_t*)(brow);
                uint32_t b1 = *(const uint32_t*)(brow + 8);
                #pragma unroll
                for (int i = 0; i < 4; i++)
                    mma16(c[i][j], a[i][0], a[i][1], a[i][2], a[i][3], b0, b1);
            }
        }
    }

    // ---- epilogue ----
    #pragma unroll
    for (int i = 0; i < 4; i++) {
        const int gm0 = m0 + wm + i * 16 + r;     // rows for c0/c1; +8 for c2/c3
        if (mode == 0) {
            const int b = gm0 >> 11;
            const int t = gm0 & 2047;
            #pragma unroll
            for (int j = 0; j < 4; j++) {
                const int col = n0 + wn + j * 8 + qd * 2;
                const int mat = col >> 10;
                const int rem = col & 1023;
                const int h   = rem >> 6;
                const int d   = rem & 63;
                __half* base = (mat == 0) ? g_qh : (mat == 1 ? g_kh : g_vh);
                const float sc = (mat == 0) ? QSCALE : 1.0f;
                size_t o0 = ((size_t)((b * 16 + h) * 2048 + t)) * 64 + d;
                *(uint32_t*)(base + o0) =
                    f2h2(c[i][j][0] * sc, c[i][j][1] * sc);
                *(uint32_t*)(base + o0 + 8 * 64) =
                    f2h2(c[i][j][2] * sc, c[i][j][3] * sc);
            }
        } else {
            #pragma unroll
            for (int j = 0; j < 4; j++) {
                const int col = n0 + wn + j * 8 + qd * 2;
                float2 bv = *(const float2*)(bias + col);
                float* d0 = out + (size_t)gm0 * EE + col;
                *(float2*)d0            = make_float2(c[i][j][0] + bv.x, c[i][j][1] + bv.y);
                *(float2*)(d0 + 8 * EE) = make_float2(c[i][j][2] + bv.x, c[i][j][3] + bv.y);
            }
        }
    }
}

// ---------------------------------------------------------------------------
// Causal flash attention — UNCHANGED round-13 configuration (static softmax,
// f16-accum S, ldmatrix.x4 frags, register-resident P, j-pair causal skip,
// MUFU ex2). Measured 102 us, at the HMMA wall.
// ---------------------------------------------------------------------------
#define AM 128
#define SK 72
#define KVBUF (64 * SK)

__global__ __launch_bounds__(256, 2) void attn_kernel()
{
    extern __shared__ __half smk[];
    __half* K0 = smk;                  // [2][64][72]
    __half* V0 = smk + 2 * KVBUF;      // [2][64][72]

    const uint32_t k0a = smem_u32(K0);
    const uint32_t v0a = smem_u32(V0);

    const int bh = blockIdx.x;
    const int b  = bh >> 4;
    const int h  = bh & 15;
    const int q0 = TT - AM - blockIdx.y * AM;   // y=0 -> longest; global LPT

    const int tid  = threadIdx.x;
    const int lane = tid & 31;
    const int wid  = tid >> 5;
    const int wm   = wid * 16;
    const int r    = lane >> 2;
    const int qd   = lane & 3;

    const __half* qg = g_qh + ((size_t)bh * TT + q0) * HD;
    const __half* kg = g_kh + (size_t)bh * TT * HD;
    const __half* vg = g_vh + (size_t)bh * TT * HD;

    auto issueKV = [&](int t) {
        const int p  = t & 1;
        const int s0 = t * 64;
        #pragma unroll
        for (int rr = 0; rr < 2; rr++) {
            int it  = tid + 256 * rr;
            int row = it >> 3;
            int c8  = it & 7;
            uint32_t off = (uint32_t)(p * KVBUF + row * SK + c8 * 8) * 2u;
            CP16(k0a + off, kg + (size_t)(s0 + row) * 64 + c8 * 8);
            CP16(v0a + off, vg + (size_t)(s0 + row) * 64 + c8 * 8);
        }
        CP_COMMIT();
    };

    const int nt = q0 / 64 + 2;
    issueKV(0);

    uint32_t qa[4][4];
    {
        const __half* q0p = qg + (size_t)(wm + r) * 64 + 2 * qd;
        #pragma unroll
        for (int s = 0; s < 4; s++) {
            qa[s][0] = *(const uint32_t*)(q0p + s * 16);
            qa[s][1] = *(const uint32_t*)(q0p + 8 * 64 + s * 16);
            qa[s][2] = *(const uint32_t*)(q0p + s * 16 + 8);
            qa[s][3] = *(const uint32_t*)(q0p + 8 * 64 + s * 16 + 8);
        }
    }

    const int k_rowgrp = (lane >> 4) & 1;
    const int k_row    = lane & 7;
    const int k_koff   = (lane >> 3) & 1;
    const int v_row    = lane & 15;
    const int v_cg     = lane >> 4;

    float o[8][4] = {};
    float l0 = 0.f, l1 = 0.f;

    for (int t = 0; t < nt; t++) {
        const int p  = t & 1;
        const int s0 = t * 64;
        if (t + 1 < nt) { issueKV(t + 1); CP_WAIT1(); }
        else            { CP_WAIT0(); }
        __syncthreads();

        const int lim = q0 + wm + 15 - s0;
        if (lim >= 0) {
            const uint32_t ksa = k0a + (uint32_t)(p * KVBUF) * 2u;
            const uint32_t vsa = v0a + (uint32_t)(p * KVBUF) * 2u;
            const bool full = (s0 + 63 <= q0 + wm);

            if (full) {
                uint32_t ch[8][2];
                #pragma unroll
                for (int j = 0; j < 8; j++) { ch[j][0] = 0u; ch[j][1] = 0u; }

                #pragma unroll
                for (int s = 0; s < 4; s++) {
                    #pragma unroll
                    for (int jb = 0; jb < 8; jb += 2) {
                        uint32_t kaddr = ksa + (uint32_t)(
                            ((jb + k_rowgrp) * 8 + k_row) * SK + s * 16 + k_koff * 8) * 2u;
                        uint32_t b0, b1, b2, b3;
                        LDSM_X4(b0, b1, b2, b3, kaddr);
                        mma16h(ch[jb],     qa[s][0], qa[s][1], qa[s][2], qa[s][3], b0, b1);
                        mma16h(ch[jb + 1], qa[s][0], qa[s][1], qa[s][2], qa[s][3], b2, b3);
                    }
                }

                uint32_t ph[4][4];
                #pragma unroll
                for (int j = 0; j < 8; j++) {
                    float2 v01 = __half22float2(*(__half2*)&ch[j][0]);
                    float2 v23 = __half22float2(*(__half2*)&ch[j][1]);
                    v01.x = ex2(v01.x);  v01.y = ex2(v01.y);
                    v23.x = ex2(v23.x);  v23.y = ex2(v23.y);
                    l0 += v01.x + v01.y;
                    l1 += v23.x + v23.y;
                    const int s_ = j >> 1;
                    if ((j & 1) == 0) {
                        ph[s_][0] = f2h2(v01.x, v01.y);
                        ph[s_][1] = f2h2(v23.x, v23.y);
                    } else {
                        ph[s_][2] = f2h2(v01.x, v01.y);
                        ph[s_][3] = f2h2(v23.x, v23.y);
                    }
                }

                #pragma unroll
                for (int s = 0; s < 4; s++) {
                    #pragma unroll
                    for (int jb = 0; jb < 8; jb += 2) {
                        uint32_t vaddr = vsa + (uint32_t)(
                            (s * 16 + v_row) * SK + (jb + v_cg) * 8) * 2u;
                        uint32_t vb0, vb1, vb2, vb3;
                        LDSM_X4T(vb0, vb1, vb2, vb3, vaddr);
                        mma16(o[jb],     ph[s][0], ph[s][1], ph[s][2], ph[s][3], vb0, vb1);
                        mma16(o[jb + 1], ph[s][0], ph[s][1], ph[s][2], ph[s][3], vb2, vb3);
                    }
                }
            } else {
                const int spairs = min(4, (lim >> 4) + 1);

                uint32_t ch[8][2];
                #pragma unroll
                for (int j = 0; j < 8; j++) { ch[j][0] = 0u; ch[j][1] = 0u; }

                for (int sp = 0; sp < spairs; sp++) {
                    const int jb = sp * 2;
                    #pragma unroll
                    for (int s = 0; s < 4; s++) {
                        uint32_t kaddr = ksa + (uint32_t)(
                            ((jb + k_rowgrp) * 8 + k_row) * SK + s * 16 + k_koff * 8) * 2u;
                        uint32_t b0, b1, b2, b3;
                        LDSM_X4(b0, b1, b2, b3, kaddr);
                        mma16h(ch[jb],     qa[s][0], qa[s][1], qa[s][2], qa[s][3], b0, b1);
                        mma16h(ch[jb + 1], qa[s][0], qa[s][1], qa[s][2], qa[s][3], b2, b3);
                    }
                }

                const int row0 = q0 + wm + r, row1 = row0 + 8;
                uint32_t ph[4][4];
                for (int sp = 0; sp < spairs; sp++) {
                    #pragma unroll
                    for (int jj = 0; jj < 2; jj++) {
                        const int j = sp * 2 + jj;
                        float2 v01 = __half22float2(*(__half2*)&ch[j][0]);
                        float2 v23 = __half22float2(*(__half2*)&ch[j][1]);
                        const int cl = s0 + j * 8 + qd * 2;
                        if (cl     > row0) v01.x = -1e30f;
                        if (cl + 1 > row0) v01.y = -1e30f;
                        if (cl     > row1) v23.x = -1e30f;
                        if (cl + 1 > row1) v23.y = -1e30f;
                        v01.x = ex2(v01.x);  v01.y = ex2(v01.y);
                        v23.x = ex2(v23.x);  v23.y = ex2(v23.y);
                        l0 += v01.x + v01.y;
                        l1 += v23.x + v23.y;
                        if (jj == 0) {
                            ph[sp][0] = f2h2(v01.x, v01.y);
                            ph[sp][1] = f2h2(v23.x, v23.y);
                        } else {
                            ph[sp][2] = f2h2(v01.x, v01.y);
                            ph[sp][3] = f2h2(v23.x, v23.y);
                        }
                    }
                }

                for (int sp = 0; sp < spairs; sp++) {
                    #pragma unroll
                    for (int jb = 0; jb < 8; jb += 2) {
                        uint32_t vaddr = vsa + (uint32_t)(
                            (sp * 16 + v_row) * SK + (jb + v_cg) * 8) * 2u;
                        uint32_t vb0, vb1, vb2, vb3;
                        LDSM_X4T(vb0, vb1, vb2, vb3, vaddr);
                        mma16(o[jb],     ph[sp][0], ph[sp][1], ph[sp][2], ph[sp][3], vb0, vb1);
                        mma16(o[jb + 1], ph[sp][0], ph[sp][1], ph[sp][2], ph[sp][3], vb2, vb3);
                    }
                }
            }
        }
        __syncthreads();
    }

    // ---- epilogue: quad-reduce l, normalize, store half to g_atth ----
    l0 += __shfl_xor_sync(0xffffffffu, l0, 1);
    l0 += __shfl_xor_sync(0xffffffffu, l0, 2);
    l1 += __shfl_xor_sync(0xffffffffu, l1, 1);
    l1 += __shfl_xor_sync(0xffffffffu, l1, 2);
    const float inv0 = 1.0f / l0, inv1 = 1.0f / l1;
    const int t0 = q0 + wm + r;
    __half* og0 = g_atth + ((size_t)b * TT + t0) * EE + h * 64;
    __half* og1 = og0 + 8 * EE;
    #pragma unroll
    for (int j = 0; j < 8; j++) {
        *(uint32_t*)(og0 + j * 8 + qd * 2) = f2h2(o[j][0] * inv0, o[j][1] * inv0);
        *(uint32_t*)(og1 + j * 8 + qd * 2) = f2h2(o[j][2] * inv1, o[j][3] * inv1);
    }
}

// ---------------------------------------------------------------------------
extern "C" void kernel_launch(void* const* d_in, const int* in_sizes, int n_in,
                              void* d_out, int out_size)
{
    const float* x  = (const float*)d_in[0];
    const float* Wq = (const float*)d_in[1];
    const float* Wk = (const float*)d_in[2];
    const float* Wv = (const float*)d_in[3];
    const float* Wo = (const float*)d_in[4];
    const float* bo = (const float*)d_in[5];
    float* out = (float*)d_out;

    __half *wt_ptr, *att_ptr, *xh_ptr, *wo_ptr;
    cudaGetSymbolAddress((void**)&wt_ptr,  g_wth);
    cudaGetSymbolAddress((void**)&att_ptr, g_atth);
    cudaGetSymbolAddress((void**)&xh_ptr,  g_xh);
    cudaGetSymbolAddress((void**)&wo_ptr,  g_woh);

    // 1) single merged pre-pass (x convert, Wo convert, Wqkv transpose)
    prep_kernel<<<NBX + NBW + NBT, 256>>>(
        (const float4*)x,  (uint2*)xh_ptr,
        (const float4*)Wo, (uint2*)wo_ptr,
        Wq, Wk, Wv);

    const int gemm_smem = 6 * ABUF * sizeof(__half);          // 110592 B
    cudaFuncSetAttribute(gemm_h_kernel,
                         cudaFuncAttributeMaxDynamicSharedMemorySize, gemm_smem);
    const int attn_smem = 4 * KVBUF * sizeof(__half);         // 36864 B
    cudaFuncSetAttribute(attn_kernel,
                         cudaFuncAttributeMaxDynamicSharedMemorySize, attn_smem);

    // 2) QKV: [8192,3072] = g_xh @ g_wth^T  (half scatter -> g_qh/g_kh/g_vh)
    {
        dim3 grid(3 * EE / 128, (BB * TT) / 128);   // (24, 64)
        gemm_h_kernel<<<grid, 256, gemm_smem>>>(0, xh_ptr, wt_ptr, nullptr, nullptr);
    }

    // 3) attention — grid (bh, qtile): global longest-first
    {
        dim3 gridB(BB * HH, TT / AM);               // (64, 16)
        attn_kernel<<<gridB, 256, attn_smem>>>();
    }

    // 4) O projection: out = g_atth @ g_woh^T + bo
    {
        dim3 grid(EE / 128, (BB * TT) / 128);       // (8, 64)
        gemm_h_kernel<<<grid, 256, gemm_smem>>>(1, att_ptr, wo_ptr, bo, out);
    }
}

// round 17
// speedup vs baseline: 1.1582x; 1.0364x over previous
#include <cuda_runtime.h>
#include <cuda_fp16.h>
#include <cstdint>

#define BB 4
#define TT 2048
#define EE 1024
#define HH 16
#define HD 64

// softmax scale folded into Q at QKV epilogue: 1/sqrt(64) * log2(e)
#define QSCALE (0.125f * 1.44269504f)

// ---------------------------------------------------------------------------
// Scratch (device globals). All activations/weights stored fp16.
// ---------------------------------------------------------------------------
__device__ __align__(16) __half g_qh[BB * HH * TT * HD];   // [B,H,T,HD], pre-scaled
__device__ __align__(16) __half g_kh[BB * HH * TT * HD];
__device__ __align__(16) __half g_vh[BB * HH * TT * HD];
__device__ __align__(16) __half g_atth[BB * TT * EE];      // [B,T,E]
__device__ __align__(16) __half g_wth[3 * EE * EE];        // K-major qkv weights
__device__ __align__(16) __half g_xh[BB * TT * EE];        // x in fp16
__device__ __align__(16) __half g_woh[EE * EE];            // Wo in fp16

// dependency counters (zeroed by prep each replay)
__device__ int g_ctr_qkv[BB];        // +1 per QKV block of that batch (target 384)
__device__ int g_ctr_attn[BB * 16];  // +1 per attention block of (b,rowblk) (target 16)

// ---------------------------------------------------------------------------
// Helpers
// ---------------------------------------------------------------------------
__device__ __forceinline__ uint32_t smem_u32(const void* p) {
    uint32_t a;
    asm("{ .reg .u64 t; cvta.to.shared.u64 t, %1; cvt.u32.u64 %0, t; }"
        : "=r"(a) : "l"(p));
    return a;
}

__device__ __forceinline__ uint32_t f2h2(float lo, float hi) {
    __half2 h = __floats2half2_rn(lo, hi);
    return *(uint32_t*)&h;
}

__device__ __forceinline__ float ex2(float x) {
    float y;
    asm("ex2.approx.ftz.f32 %0, %1;" : "=f"(y) : "f"(x));
    return y;
}

// m16n8k16 f16 MMA, f32 accumulate
__device__ __forceinline__ void mma16(float c[4],
                                      uint32_t a0, uint32_t a1, uint32_t a2, uint32_t a3,
                                      uint32_t b0, uint32_t b1) {
    asm volatile(
        "mma.sync.aligned.m16n8k16.row.col.f32.f16.f16.f32 "
        "{%0,%1,%2,%3},{%4,%5,%6,%7},{%8,%9},{%0,%1,%2,%3};"
        : "+f"(c[0]), "+f"(c[1]), "+f"(c[2]), "+f"(c[3])
        : "r"(a0), "r"(a1), "r"(a2), "r"(a3), "r"(b0), "r"(b1));
}

// m16n8k16 f16 MMA, f16 accumulate (same pipe rate; saves unpack in S)
__device__ __forceinline__ void mma16h(uint32_t c[2],
                                       uint32_t a0, uint32_t a1, uint32_t a2, uint32_t a3,
                                       uint32_t b0, uint32_t b1) {
    asm volatile(
        "mma.sync.aligned.m16n8k16.row.col.f16.f16.f16.f16 "
        "{%0,%1},{%2,%3,%4,%5},{%6,%7},{%0,%1};"
        : "+r"(c[0]), "+r"(c[1])
        : "r"(a0), "r"(a1), "r"(a2), "r"(a3), "r"(b0), "r"(b1));
}

#define LDSM_X4(r0, r1, r2, r3, addr) \
    asm volatile("ldmatrix.sync.aligned.m8n8.x4.shared.b16 {%0,%1,%2,%3}, [%4];" \
                 : "=r"(r0), "=r"(r1), "=r"(r2), "=r"(r3) : "r"(addr))
#define LDSM_X4T(r0, r1, r2, r3, addr) \
    asm volatile("ldmatrix.sync.aligned.m8n8.x4.trans.shared.b16 {%0,%1,%2,%3}, [%4];" \
                 : "=r"(r0), "=r"(r1), "=r"(r2), "=r"(r3) : "r"(addr))

#define CP16(dst, src) \
    asm volatile("cp.async.cg.shared.global [%0], [%1], 16;" :: "r"(dst), "l"(src))
#define CP_COMMIT()  asm volatile("cp.async.commit_group;" ::: "memory")
#define CP_WAIT1()   asm volatile("cp.async.wait_group 1;" ::: "memory")
#define CP_WAIT0()   asm volatile("cp.async.wait_group 0;" ::: "memory")

// spin until *ctr >= target (tid 0 only), then block-wide acquire
__device__ __forceinline__ void block_wait(volatile int* ctr, int target) {
    if (threadIdx.x == 0) {
        while (*ctr < target) __nanosleep(128);
        __threadfence();
    }
    __syncthreads();
}

// ---------------------------------------------------------------------------
// Single merged pre-pass: zero counters, x -> g_xh, Wo -> g_woh,
// Wq/Wk/Wv -> g_wth (K-major).
// ---------------------------------------------------------------------------
#define NBX 8192
#define NBW 1024
#define NBT 3072

__global__ __launch_bounds__(256) void prep_kernel(
    const float4* __restrict__ x4,  uint2* __restrict__ xh4,
    const float4* __restrict__ wo4, uint2* __restrict__ woh4,
    const float* __restrict__ Wq,
    const float* __restrict__ Wk,
    const float* __restrict__ Wv)
{
    const int bid = blockIdx.x;
    const int tid = threadIdx.x;

    if (bid == 0) {   // zero dependency counters for this replay
        if (tid < BB) g_ctr_qkv[tid] = 0;
        else if (tid < BB + BB * 16) g_ctr_attn[tid - BB] = 0;
    }

    if (bid < NBX) {
        int i = bid * 256 + tid;
        float4 v = x4[i];
        xh4[i] = make_uint2(f2h2(v.x, v.y), f2h2(v.z, v.w));
    } else if (bid < NBX + NBW) {
        int i = (bid - NBX) * 256 + tid;
        float4 v = wo4[i];
        woh4[i] = make_uint2(f2h2(v.x, v.y), f2h2(v.z, v.w));
    } else {
        const int bt  = bid - (NBX + NBW);
        const int m   = bt >> 10;
        const int rem = bt & 1023;
        const int yy  = rem >> 5;
        const int k0  = (rem & 31) * 32;
        const int h   = yy >> 1;
        const int d0  = (yy & 1) * 32;

        const float* Ws[3] = {Wq, Wk, Wv};
        __shared__ float tile[32][33];
        const int tx = tid & 31;
        const int ty = tid >> 5;

        const float* src = Ws[m] + (size_t)h * EE * HD;
        #pragma unroll
        for (int i = 0; i < 4; i++)
            tile[ty + 8 * i][tx] = src[(size_t)(k0 + ty + 8 * i) * HD + d0 + tx];
        __syncthreads();

        #pragma unroll
        for (int i = 0; i < 4; i++) {
            int n = m * 1024 + h * 64 + d0 + ty + 8 * i;
            g_wth[(size_t)n * EE + k0 + tx] = __float2half_rn(tile[tx][ty + 8 * i]);
        }
    }
}

// ---------------------------------------------------------------------------
// GEMM body (round-16 proven): 128x128 tile, 8 warps, 3-stage cp.async,
// single barrier per chunk, scalar-LDS fragments, f32 accumulate.
// mode 0: QKV; mode 1: OPROJ.
// ---------------------------------------------------------------------------
#define SA 72
#define ABUF (128 * SA)
#define NC 16

__device__ __forceinline__ void gemm_body(
    int mode, int m0, int n0, __half* smh,
    const __half* __restrict__ A,
    const __half* __restrict__ Bsrc,
    const float* __restrict__ bias,
    float* __restrict__ out)
{
    __half* Ah = smh;
    __half* Bh = smh + 3 * ABUF;

    const int tid  = threadIdx.x;
    const int lane = tid & 31;
    const int wid  = tid >> 5;
    const int wm   = (wid >> 2) * 64;
    const int wn   = (wid & 3) * 32;
    const int r    = lane >> 2;
    const int qd   = lane & 3;

    const uint32_t ah0 = smem_u32(Ah);
    const uint32_t bh0 = smem_u32(Bh);

    float c[4][4][4] = {};

    auto issue = [&](int cidx) {
        const int p  = cidx % 3;
        const int k0 = cidx * 64;
        #pragma unroll
        for (int rr = 0; rr < 4; rr++) {
            int it  = tid + 256 * rr;
            int row = it >> 3;
            int c8  = it & 7;
            uint32_t off = (uint32_t)(p * ABUF + row * SA + c8 * 8) * 2u;
            CP16(ah0 + off, A + (size_t)(m0 + row) * EE + k0 + c8 * 8);
            CP16(bh0 + off, Bsrc + (size_t)(n0 + row) * EE + k0 + c8 * 8);
        }
        CP_COMMIT();
    };

    issue(0);
    issue(1);

    for (int cc = 0; cc < NC; cc++) {
        if (cc == NC - 1) { CP_WAIT0(); }
        else              { CP_WAIT1(); }
        __syncthreads();
        if (cc + 2 < NC) issue(cc + 2);

        const int p = cc % 3;
        const __half* ap = Ah + p * ABUF;
        const __half* bp = Bh + p * ABUF;
        #pragma unroll
        for (int s = 0; s < 4; s++) {
            uint32_t a[4][4];
            #pragma unroll
            for (int i = 0; i < 4; i++) {
                const __half* arow = ap + (wm + i * 16 + r) * SA + s * 16 + 2 * qd;
                a[i][0] = *(const uint32_t*)(arow);
                a[i][1] = *(const uint32_t*)(arow + 8 * SA);
                a[i][2] = *(const uint32_t*)(arow + 8);
                a[i][3] = *(const uint32_t*)(arow + 8 * SA + 8);
            }
            #pragma unroll
            for (int j = 0; j < 4; j++) {
                const __half* brow = bp + (wn + j * 8 + r) * SA + s * 16 + 2 * qd;
                uint32_t b0 = *(const uint32_t*)(brow);
                uint32_t b1 = *(const uint32_t*)(brow + 8);
                #pragma unroll
                for (int i = 0; i < 4; i++)
                    mma16(c[i][j], a[i][0], a[i][1], a[i][2], a[i][3], b0, b1);
            }
        }
    }

    #pragma unroll
    for (int i = 0; i < 4; i++) {
        const int gm0 = m0 + wm + i * 16 + r;
        if (mode == 0) {
            const int b = gm0 >> 11;
            const int t = gm0 & 2047;
            #pragma unroll
            for (int j = 0; j < 4; j++) {
                const int col = n0 + wn + j * 8 + qd * 2;
                const int mat = col >> 10;
                const int rem = col & 1023;
                const int h   = rem >> 6;
                const int d   = rem & 63;
                __half* base = (mat == 0) ? g_qh : (mat == 1 ? g_kh : g_vh);
                const float sc = (mat == 0) ? QSCALE : 1.0f;
                size_t o0 = ((size_t)((b * 16 + h) * 2048 + t)) * 64 + d;
                *(uint32_t*)(base + o0) =
                    f2h2(c[i][j][0] * sc, c[i][j][1] * sc);
                *(uint32_t*)(base + o0 + 8 * 64) =
                    f2h2(c[i][j][2] * sc, c[i][j][3] * sc);
            }
        } else {
            #pragma unroll
            for (int j = 0; j < 4; j++) {
                const int col = n0 + wn + j * 8 + qd * 2;
                float2 bv = *(const float2*)(bias + col);
                float* d0 = out + (size_t)gm0 * EE + col;
                *(float2*)d0            = make_float2(c[i][j][0] + bv.x, c[i][j][1] + bv.y);
                *(float2*)(d0 + 8 * EE) = make_float2(c[i][j][2] + bv.x, c[i][j][3] + bv.y);
            }
        }
    }
}

// ---------------------------------------------------------------------------
// Attention body (round-13 proven): static softmax, f16-accum S, ldmatrix.x4
// frags, register-resident P, j-pair causal skip, MUFU ex2.
// ---------------------------------------------------------------------------
#define AM 128
#define SK 72
#define KVBUF (64 * SK)

__device__ __forceinline__ void attn_body(int bh, int y, __half* smk)
{
    __half* K0 = smk;
    __half* V0 = smk + 2 * KVBUF;

    const uint32_t k0a = smem_u32(K0);
    const uint32_t v0a = smem_u32(V0);

    const int b  = bh >> 4;
    const int h  = bh & 15;
    const int q0 = TT - AM - y * AM;

    const int tid  = threadIdx.x;
    const int lane = tid & 31;
    const int wid  = tid >> 5;
    const int wm   = wid * 16;
    const int r    = lane >> 2;
    const int qd   = lane & 3;

    const __half* qg = g_qh + ((size_t)bh * TT + q0) * HD;
    const __half* kg = g_kh + (size_t)bh * TT * HD;
    const __half* vg = g_vh + (size_t)bh * TT * HD;

    auto issueKV = [&](int t) {
        const int p  = t & 1;
        const int s0 = t * 64;
        #pragma unroll
        for (int rr = 0; rr < 2; rr++) {
            int it  = tid + 256 * rr;
            int row = it >> 3;
            int c8  = it & 7;
            uint32_t off = (uint32_t)(p * KVBUF + row * SK + c8 * 8) * 2u;
            CP16(k0a + off, kg + (size_t)(s0 + row) * 64 + c8 * 8);
            CP16(v0a + off, vg + (size_t)(s0 + row) * 64 + c8 * 8);
        }
        CP_COMMIT();
    };

    const int nt = q0 / 64 + 2;
    issueKV(0);

    uint32_t qa[4][4];
    {
        const __half* q0p = qg + (size_t)(wm + r) * 64 + 2 * qd;
        #pragma unroll
        for (int s = 0; s < 4; s++) {
            qa[s][0] = *(const uint32_t*)(q0p + s * 16);
            qa[s][1] = *(const uint32_t*)(q0p + 8 * 64 + s * 16);
            qa[s][2] = *(const uint32_t*)(q0p + s * 16 + 8);
            qa[s][3] = *(const uint32_t*)(q0p + 8 * 64 + s * 16 + 8);
        }
    }

    const int k_rowgrp = (lane >> 4) & 1;
    const int k_row    = lane & 7;
    const int k_koff   = (lane >> 3) & 1;
    const int v_row    = lane & 15;
    const int v_cg     = lane >> 4;

    float o[8][4] = {};
    float l0 = 0.f, l1 = 0.f;

    for (int t = 0; t < nt; t++) {
        const int p  = t & 1;
        const int s0 = t * 64;
        if (t + 1 < nt) { issueKV(t + 1); CP_WAIT1(); }
        else            { CP_WAIT0(); }
        __syncthreads();

        const int lim = q0 + wm + 15 - s0;
        if (lim >= 0) {
            const uint32_t ksa = k0a + (uint32_t)(p * KVBUF) * 2u;
            const uint32_t vsa = v0a + (uint32_t)(p * KVBUF) * 2u;
            const bool full = (s0 + 63 <= q0 + wm);

            if (full) {
                uint32_t ch[8][2];
                #pragma unroll
                for (int j = 0; j < 8; j++) { ch[j][0] = 0u; ch[j][1] = 0u; }

                #pragma unroll
                for (int s = 0; s < 4; s++) {
                    #pragma unroll
                    for (int jb = 0; jb < 8; jb += 2) {
                        uint32_t kaddr = ksa + (uint32_t)(
                            ((jb + k_rowgrp) * 8 + k_row) * SK + s * 16 + k_koff * 8) * 2u;
                        uint32_t b0, b1, b2, b3;
                        LDSM_X4(b0, b1, b2, b3, kaddr);
                        mma16h(ch[jb],     qa[s][0], qa[s][1], qa[s][2], qa[s][3], b0, b1);
                        mma16h(ch[jb + 1], qa[s][0], qa[s][1], qa[s][2], qa[s][3], b2, b3);
                    }
                }

                uint32_t ph[4][4];
                #pragma unroll
                for (int j = 0; j < 8; j++) {
                    float2 v01 = __half22float2(*(__half2*)&ch[j][0]);
                    float2 v23 = __half22float2(*(__half2*)&ch[j][1]);
                    v01.x = ex2(v01.x);  v01.y = ex2(v01.y);
                    v23.x = ex2(v23.x);  v23.y = ex2(v23.y);
                    l0 += v01.x + v01.y;
                    l1 += v23.x + v23.y;
                    const int s_ = j >> 1;
                    if ((j & 1) == 0) {
                        ph[s_][0] = f2h2(v01.x, v01.y);
                        ph[s_][1] = f2h2(v23.x, v23.y);
                    } else {
                        ph[s_][2] = f2h2(v01.x, v01.y);
                        ph[s_][3] = f2h2(v23.x, v23.y);
                    }
                }

                #pragma unroll
                for (int s = 0; s < 4; s++) {
                    #pragma unroll
                    for (int jb = 0; jb < 8; jb += 2) {
                        uint32_t vaddr = vsa + (uint32_t)(
                            (s * 16 + v_row) * SK + (jb + v_cg) * 8) * 2u;
                        uint32_t vb0, vb1, vb2, vb3;
                        LDSM_X4T(vb0, vb1, vb2, vb3, vaddr);
                        mma16(o[jb],     ph[s][0], ph[s][1], ph[s][2], ph[s][3], vb0, vb1);
                        mma16(o[jb + 1], ph[s][0], ph[s][1], ph[s][2], ph[s][3], vb2, vb3);
                    }
                }
            } else {
                const int spairs = min(4, (lim >> 4) + 1);

                uint32_t ch[8][2];
                #pragma unroll
                for (int j = 0; j < 8; j++) { ch[j][0] = 0u; ch[j][1] = 0u; }

                for (int sp = 0; sp < spairs; sp++) {
                    const int jb = sp * 2;
                    #pragma unroll
                    for (int s = 0; s < 4; s++) {
                        uint32_t kaddr = ksa + (uint32_t)(
                            ((jb + k_rowgrp) * 8 + k_row) * SK + s * 16 + k_koff * 8) * 2u;
                        uint32_t b0, b1, b2, b3;
                        LDSM_X4(b0, b1, b2, b3, kaddr);
                        mma16h(ch[jb],     qa[s][0], qa[s][1], qa[s][2], qa[s][3], b0, b1);
                        mma16h(ch[jb + 1], qa[s][0], qa[s][1], qa[s][2], qa[s][3], b2, b3);
                    }
                }

                const int row0 = q0 + wm + r, row1 = row0 + 8;
                uint32_t ph[4][4];
                for (int sp = 0; sp < spairs; sp++) {
                    #pragma unroll
                    for (int jj = 0; jj < 2; jj++) {
                        const int j = sp * 2 + jj;
                        float2 v01 = __half22float2(*(__half2*)&ch[j][0]);
                        float2 v23 = __half22float2(*(__half2*)&ch[j][1]);
                        const int cl = s0 + j * 8 + qd * 2;
                        if (cl     > row0) v01.x = -1e30f;
                        if (cl + 1 > row0) v01.y = -1e30f;
                        if (cl     > row1) v23.x = -1e30f;
                        if (cl + 1 > row1) v23.y = -1e30f;
                        v01.x = ex2(v01.x);  v01.y = ex2(v01.y);
                        v23.x = ex2(v23.x);  v23.y = ex2(v23.y);
                        l0 += v01.x + v01.y;
                        l1 += v23.x + v23.y;
                        if (jj == 0) {
                            ph[sp][0] = f2h2(v01.x, v01.y);
                            ph[sp][1] = f2h2(v23.x, v23.y);
                        } else {
                            ph[sp][2] = f2h2(v01.x, v01.y);
                            ph[sp][3] = f2h2(v23.x, v23.y);
                        }
                    }
                }

                for (int sp = 0; sp < spairs; sp++) {
                    #pragma unroll
                    for (int jb = 0; jb < 8; jb += 2) {
                        uint32_t vaddr = vsa + (uint32_t)(
                            (sp * 16 + v_row) * SK + (jb + v_cg) * 8) * 2u;
                        uint32_t vb0, vb1, vb2, vb3;
                        LDSM_X4T(vb0, vb1, vb2, vb3, vaddr);
                        mma16(o[jb],     ph[sp][0], ph[sp][1], ph[sp][2], ph[sp][3], vb0, vb1);
                        mma16(o[jb + 1], ph[sp][0], ph[sp][1], ph[sp][2], ph[sp][3], vb2, vb3);
                    }
                }
            }
        }
        __syncthreads();
    }

    l0 += __shfl_xor_sync(0xffffffffu, l0, 1);
    l0 += __shfl_xor_sync(0xffffffffu, l0, 2);
    l1 += __shfl_xor_sync(0xffffffffu, l1, 1);
    l1 += __shfl_xor_sync(0xffffffffu, l1, 2);
    const float inv0 = 1.0f / l0, inv1 = 1.0f / l1;
    const int t0 = q0 + wm + r;
    __half* og0 = g_atth + ((size_t)b * TT + t0) * EE + h * 64;
    __half* og1 = og0 + 8 * EE;
    #pragma unroll
    for (int j = 0; j < 8; j++) {
        *(uint32_t*)(og0 + j * 8 + qd * 2) = f2h2(o[j][0] * inv0, o[j][1] * inv0);
        *(uint32_t*)(og1 + j * 8 + qd * 2) = f2h2(o[j][2] * inv1, o[j][3] * inv1);
    }
}

// ---------------------------------------------------------------------------
// Fused kernel: [0,1536) QKV (batch-major) | [1536,2560) attention (LPT) |
// [2560,3072) O-proj. Cross-phase dependencies via device counters — later
// phases backfill the earlier phases' partial last waves.
// ---------------------------------------------------------------------------
#define NQKV 1536
#define NATT 1024

__global__ __launch_bounds__(256, 2) void fused_kernel(
    const float* __restrict__ bias, float* __restrict__ out)
{
    extern __shared__ __half smh[];
    const int id = blockIdx.x;

    if (id < NQKV) {
        // -------- QKV: m batch-major so batch counters fill early ----------
        const int m0 = (id / 24) * 128;
        const int n0 = (id % 24) * 128;
        gemm_body(0, m0, n0, smh, g_xh, g_wth, nullptr, nullptr);
        __syncthreads();
        if (threadIdx.x == 0) {
            __threadfence();
            atomicAdd(&g_ctr_qkv[m0 >> 11], 1);
        }
    } else if (id < NQKV + NATT) {
        // -------- attention: wait for its batch's QKV ----------------------
        const int aid = id - NQKV;
        const int bh  = aid & 63;
        const int y   = aid >> 6;           // y=0 first => global LPT
        const int b   = bh >> 4;
        block_wait(&g_ctr_qkv[b], 384);
        attn_body(bh, y, smh);
        __syncthreads();
        if (threadIdx.x == 0) {
            __threadfence();
            const int q0 = TT - AM - y * AM;
            atomicAdd(&g_ctr_attn[b * 16 + (q0 >> 7)], 1);
        }
    } else {
        // -------- O-proj: wait for all 16 heads of its 128-row block -------
        const int idx = id - (NQKV + NATT);
        const int n0  = (idx & 7) * 128;
        const int m0  = (idx >> 3) * 128;
        const int b   = m0 >> 11;
        const int rb  = (m0 & 2047) >> 7;
        block_wait(&g_ctr_attn[b * 16 + rb], 16);
        gemm_body(1, m0, n0, smh, g_atth, g_woh, bias, out);
    }
}

// ---------------------------------------------------------------------------
extern "C" void kernel_launch(void* const* d_in, const int* in_sizes, int n_in,
                              void* d_out, int out_size)
{
    const float* x  = (const float*)d_in[0];
    const float* Wq = (const float*)d_in[1];
    const float* Wk = (const float*)d_in[2];
    const float* Wv = (const float*)d_in[3];
    const float* Wo = (const float*)d_in[4];
    const float* bo = (const float*)d_in[5];
    float* out = (float*)d_out;

    __half *xh_ptr, *wo_ptr;
    cudaGetSymbolAddress((void**)&xh_ptr, g_xh);
    cudaGetSymbolAddress((void**)&wo_ptr, g_woh);

    // 1) merged pre-pass (counter zeroing, x/Wo convert, Wqkv transpose)
    prep_kernel<<<NBX + NBW + NBT, 256>>>(
        (const float4*)x,  (uint2*)xh_ptr,
        (const float4*)Wo, (uint2*)wo_ptr,
        Wq, Wk, Wv);

    // 2) fused QKV + attention + O-proj
    const int fused_smem = 6 * ABUF * sizeof(__half);   // 110592 B (2 blocks/SM)
    cudaFuncSetAttribute(fused_kernel,
                         cudaFuncAttributeMaxDynamicSharedMemorySize, fused_smem);
    fused_kernel<<<NQKV + NATT + 512, 256, fused_smem>>>(bo, out);
}